// round 17
// baseline (speedup 1.0000x reference)
#include <cuda_runtime.h>
#include <cuda_fp16.h>
#include <stdint.h>
#include <math.h>

// Problem constants
#define TT 256   // T (time steps)
#define BB 128   // batch
#define SS 512   // memory sequence length
#define DD 256   // EMBED = HID = ENC = DEC
#define GG 1024  // 4*HID gates
#define NKZ 2    // per-step gate-gemm split (ctx, h)

// ---------------- scratch (__device__ globals; no allocation allowed) ----------------
__device__ __half g_memproj[BB * SS * DD];  // [b][s][d] fp16 : 34 MB
__device__ __half g_memt[BB * SS * DD];     // [b][s][e] fp16 : 34 MB
__device__ __half g_w16[GG * 768];          // [j][k] fp16 gate weights (0-511 W_ih, 512-767 W_hh)
__device__ float g_gpre[TT * BB * GG];      // precomputed tgt gate partial : 134 MB
__device__ float g_h[2][BB * DD];           // double-buffered by step parity
__device__ float g_c[2][BB * DD];
__device__ float2 g_stats[4][BB];           // per-chunk softmax stats (max, sum)
__device__ float g_ctxp[4][BB * DD];        // UNNORMALIZED ctx partials per s-chunk
__device__ float g_gp[NKZ][BB * GG];        // per-step gate partials (ctx, h)

// ---------------- fast math ----------------
__device__ __forceinline__ float tanh_approx(float x) {
    float y;
    asm("tanh.approx.f32 %0, %1;" : "=f"(y) : "f"(x));
    return y;
}
__device__ __forceinline__ float fast_tanh(float x) {
    x = fminf(fmaxf(x, -15.f), 15.f);
    float e = __expf(2.f * x);
    return __fdividef(e - 1.f, e + 1.f);
}
__device__ __forceinline__ float fast_sigmoid(float x) {
    return __fdividef(1.f, 1.f + __expf(-x));
}
// L2 keep-resident policy (once per thread)
__device__ __forceinline__ uint64_t mk_evict_last_policy() {
    uint64_t pol;
    asm("createpolicy.fractional.L2::evict_last.b64 %0, 1.0;" : "=l"(pol));
    return pol;
}
// 16B streaming load with L2 evict_last cache hint
__device__ __forceinline__ uint4 ldg_el(const void* p, uint64_t pol) {
    uint4 v;
    asm("ld.global.nc.L2::cache_hint.v4.u32 {%0,%1,%2,%3}, [%4], %5;"
        : "=r"(v.x), "=r"(v.y), "=r"(v.z), "=r"(v.w) : "l"(p), "l"(pol));
    return v;
}

// ---------------- fused prologue: memproj GEMM + transposes + weight conversion + init ----------------
__global__ __launch_bounds__(256) void k_pre(const float* __restrict__ memory,
                                             const float* __restrict__ W_attn,
                                             const float* __restrict__ b_attn,
                                             const float* __restrict__ W_ih,
                                             const float* __restrict__ W_hh,
                                             float* __restrict__ out0) {
    __shared__ __align__(16) float Ash[32][68];
    __shared__ __align__(16) float Bsh[32][68];
    int tid = threadIdx.x;
    int tx = tid & 15, ty = tid >> 4;
    int n0 = blockIdx.x * 64;
    int m0 = blockIdx.y * 64;
    int L = blockIdx.y * 4 + blockIdx.x;

    if (L < 128) {
        int idx = L * 256 + tid;
        g_h[0][idx] = 0.f;
        g_c[0][idx] = 0.f;
        out0[idx] = 0.f;
    }

    if (L < GG) {
        int j = L;
#pragma unroll
        for (int i = 0; i < 3; i++) {
            int k = tid + i * 256;
            float wv = (k < 512) ? W_ih[(size_t)j * 512 + k] : W_hh[(size_t)j * 256 + (k - 512)];
            g_w16[(size_t)j * 768 + k] = __float2half(wv);
        }
    }

    {
        int b = L >> 5;
        int sc = L & 31;
#pragma unroll
        for (int i = 0; i < 16; i++) {
            int s = sc * 16 + i;
            g_memt[(size_t)b * SS * DD + (size_t)s * DD + tid] =
                __float2half(memory[((size_t)s * BB + b) * DD + tid]);
        }
    }

    float acc[4][4];
#pragma unroll
    for (int i = 0; i < 4; i++)
#pragma unroll
        for (int j = 0; j < 4; j++) acc[i][j] = 0.f;

    for (int k0 = 0; k0 < DD; k0 += 32) {
#pragma unroll
        for (int i = 0; i < 8; i++) {
            int idx = tid + i * 256;
            int e = idx & 31;
            int m = idx >> 5;
            int r = m0 + m;
            int b = r >> 9;
            int s = r & 511;
            Ash[e][m] = memory[((size_t)(s * BB + b)) * DD + k0 + e];
            int d = m;
            Bsh[e][d] = W_attn[(size_t)(n0 + d) * (2 * DD) + DD + k0 + e];
        }
        __syncthreads();
#pragma unroll
        for (int k = 0; k < 32; k++) {
            float4 a = *(const float4*)&Ash[k][ty * 4];
            float4 bv = *(const float4*)&Bsh[k][tx * 4];
            float av[4] = {a.x, a.y, a.z, a.w};
            float bw[4] = {bv.x, bv.y, bv.z, bv.w};
#pragma unroll
            for (int i = 0; i < 4; i++)
#pragma unroll
                for (int j = 0; j < 4; j++) acc[i][j] = fmaf(av[i], bw[j], acc[i][j]);
        }
        __syncthreads();
    }
    float4 bias = *(const float4*)&b_attn[n0 + tx * 4];
#pragma unroll
    for (int i = 0; i < 4; i++) {
        int r = m0 + ty * 4 + i;
        __half2 h0 = __floats2half2_rn(acc[i][0] + bias.x, acc[i][1] + bias.y);
        __half2 h1 = __floats2half2_rn(acc[i][2] + bias.z, acc[i][3] + bias.w);
        __half2* dst = (__half2*)&g_memproj[(size_t)r * DD + n0 + tx * 4];
        dst[0] = h0;
        dst[1] = h1;
    }
}

// ---------------- prologue HMMA: g_gpre[r][j] = sum_k tgt_flat[r][k] * W_ih[j][k], k<256 ----------------
__global__ __launch_bounds__(128) void k_pregemm(const float* __restrict__ tgt) {
    __shared__ __align__(16) __half sA[32][264];
    __shared__ __align__(16) __half sB[32][264];

    int tid = threadIdx.x;
    int lane = tid & 31;
    int warp = tid >> 5;
    int n0 = blockIdx.x * 32;
    int m0 = blockIdx.y * 32;

#pragma unroll
    for (int i = 0; i < 16; i++) {
        int idx = tid + i * 128;
        int row = idx >> 6;
        int c4 = idx & 63;
        float4 v = *(const float4*)&tgt[(size_t)(m0 + row) * DD + c4 * 4];
        *(__half2*)&sA[row][c4 * 4]     = __floats2half2_rn(v.x, v.y);
        *(__half2*)&sA[row][c4 * 4 + 2] = __floats2half2_rn(v.z, v.w);
    }
    {
        const uint4* wb = (const uint4*)g_w16;
#pragma unroll
        for (int i = 0; i < 8; i++) {
            int idx = tid + i * 128;
            int row = idx >> 5;
            int c4 = idx & 31;
            uint4 v = wb[(size_t)(n0 + row) * 96 + c4];
            *(uint4*)&sB[row][c4 * 8] = v;
        }
    }
    __syncthreads();

    int g = lane >> 2;
    int tg = lane & 3;
    int mw = (warp >> 1) * 16;
    int nw = (warp & 1) * 16;

    float d0[4] = {0.f, 0.f, 0.f, 0.f};
    float d1[4] = {0.f, 0.f, 0.f, 0.f};

#pragma unroll
    for (int ks = 0; ks < 16; ks++) {
        int kc = ks * 16 + tg * 2;
        uint32_t a0 = *(const uint32_t*)&sA[mw + g][kc];
        uint32_t a1 = *(const uint32_t*)&sA[mw + g + 8][kc];
        uint32_t a2 = *(const uint32_t*)&sA[mw + g][kc + 8];
        uint32_t a3 = *(const uint32_t*)&sA[mw + g + 8][kc + 8];
        uint32_t b0 = *(const uint32_t*)&sB[nw + g][kc];
        uint32_t b1 = *(const uint32_t*)&sB[nw + g][kc + 8];
        uint32_t b2 = *(const uint32_t*)&sB[nw + 8 + g][kc];
        uint32_t b3 = *(const uint32_t*)&sB[nw + 8 + g][kc + 8];

        asm volatile(
            "mma.sync.aligned.m16n8k16.row.col.f32.f16.f16.f32 "
            "{%0,%1,%2,%3}, {%4,%5,%6,%7}, {%8,%9}, {%0,%1,%2,%3};\n"
            : "+f"(d0[0]), "+f"(d0[1]), "+f"(d0[2]), "+f"(d0[3])
            : "r"(a0), "r"(a1), "r"(a2), "r"(a3), "r"(b0), "r"(b1));
        asm volatile(
            "mma.sync.aligned.m16n8k16.row.col.f32.f16.f16.f32 "
            "{%0,%1,%2,%3}, {%4,%5,%6,%7}, {%8,%9}, {%0,%1,%2,%3};\n"
            : "+f"(d1[0]), "+f"(d1[1]), "+f"(d1[2]), "+f"(d1[3])
            : "r"(a0), "r"(a1), "r"(a2), "r"(a3), "r"(b2), "r"(b3));
    }

    {
        int r0 = m0 + mw + g;
        int r1 = r0 + 8;
        int c0 = n0 + nw + tg * 2;
        *(float2*)&g_gpre[(size_t)r0 * GG + c0]     = make_float2(d0[0], d0[1]);
        *(float2*)&g_gpre[(size_t)r1 * GG + c0]     = make_float2(d0[2], d0[3]);
        *(float2*)&g_gpre[(size_t)r0 * GG + c0 + 8] = make_float2(d1[0], d1[1]);
        *(float2*)&g_gpre[(size_t)r1 * GG + c0 + 8] = make_float2(d1[2], d1[3]);
    }
}

// ---------------- per-step fused: LSTM-cell(t-1) + energy + local softmax + ctx partial ----------------
// grid (4 s-chunks, 128 b), 512 thr. Flash-style: chunk-local softmax, exact combine in k_gemm.
__global__ __launch_bounds__(512) void k_att(const float* __restrict__ W_attn,
                                             const float* __restrict__ b_ih,
                                             const float* __restrict__ b_hh,
                                             float* __restrict__ out_prev,
                                             int t) {
    __shared__ __align__(16) float sh_h[DD];
    __shared__ __align__(16) float sh_w[DD];
    __shared__ __align__(16) float sh_e[128];      // chunk-local energies -> unnorm weights
    __shared__ float sh_red[16];
    __shared__ float sh_sum[16];
    __shared__ __align__(16) float sh_ctxp[16][264];

    int c = blockIdx.x;
    int b = blockIdx.y;
    int tid = threadIdx.x;
    int lane = tid & 31;
    int warp = tid >> 5;
    uint64_t pol = mk_evict_last_policy();

    // Phase A: cell for step t-1 (redundant across the 4 chunk-blocks; identical values)
    if (tid < DD) {
        int hd = tid;
        if (t > 1) {
            int rp = t & 1;
            int wp = (t + 1) & 1;
            size_t base = (size_t)b * GG;
            size_t pre = ((size_t)(t - 1) * BB + b) * GG;
            float vi = b_ih[hd] + b_hh[hd] + g_gpre[pre + hd];
            float vf = b_ih[hd + 256] + b_hh[hd + 256] + g_gpre[pre + hd + 256];
            float vg = b_ih[hd + 512] + b_hh[hd + 512] + g_gpre[pre + hd + 512];
            float vo = b_ih[hd + 768] + b_hh[hd + 768] + g_gpre[pre + hd + 768];
#pragma unroll
            for (int p = 0; p < NKZ; p++) {
                vi += g_gp[p][base + hd];
                vf += g_gp[p][base + hd + 256];
                vg += g_gp[p][base + hd + 512];
                vo += g_gp[p][base + hd + 768];
            }
            float gi = fast_sigmoid(vi);
            float gf = fast_sigmoid(vf);
            float gc = fast_tanh(vg);
            float go = fast_sigmoid(vo);
            float cc = gf * g_c[rp][b * DD + hd] + gi * gc;
            float hh = go * fast_tanh(cc);
            g_c[wp][b * DD + hd] = cc;
            g_h[wp][b * DD + hd] = hh;
            out_prev[b * DD + hd] = hh;
            sh_h[hd] = hh;
        } else {
            sh_h[hd] = 0.f;
        }
    }
    __syncthreads();

    // hWh[d]
    for (int dd = 0; dd < 16; dd++) {
        int d = warp * 16 + dd;
        const float* wr = &W_attn[(size_t)d * (2 * DD)];
        float acc = 0.f;
#pragma unroll
        for (int j = 0; j < 8; j++) {
            int k = lane + j * 32;
            acc = fmaf(wr[k], sh_h[k], acc);
        }
#pragma unroll
        for (int o = 16; o; o >>= 1) acc += __shfl_xor_sync(0xffffffffu, acc, o);
        if (lane == 0) sh_w[d] = acc;
    }
    __syncthreads();

    // Energy: e_sum for this chunk's 128 s -> sh_e
    {
        float4 w0 = *(const float4*)&sh_w[lane * 8];
        float4 w1 = *(const float4*)&sh_w[lane * 8 + 4];
        int sbase = c * 128;
        const uint4* mpb = (const uint4*)g_memproj;

#pragma unroll
        for (int it = 0; it < 4; it++) {
            int s1 = sbase + warp + it * 32;
            int s2 = s1 + 16;
            uint4 v1 = ldg_el(&mpb[(size_t)(b * SS + s1) * 32 + lane], pol);
            uint4 v2 = ldg_el(&mpb[(size_t)(b * SS + s2) * 32 + lane], pol);

            float2 p0 = __half22float2(*(__half2*)&v1.x);
            float2 p1 = __half22float2(*(((__half2*)&v1.x) + 1));
            float2 p2 = __half22float2(*(__half2*)&v1.z);
            float2 p3 = __half22float2(*(((__half2*)&v1.z) + 1));
            float acc1 = tanh_approx(p0.x + w0.x) + tanh_approx(p0.y + w0.y) +
                         tanh_approx(p1.x + w0.z) + tanh_approx(p1.y + w0.w) +
                         tanh_approx(p2.x + w1.x) + tanh_approx(p2.y + w1.y) +
                         tanh_approx(p3.x + w1.z) + tanh_approx(p3.y + w1.w);

            float2 q0 = __half22float2(*(__half2*)&v2.x);
            float2 q1 = __half22float2(*(((__half2*)&v2.x) + 1));
            float2 q2 = __half22float2(*(__half2*)&v2.z);
            float2 q3 = __half22float2(*(((__half2*)&v2.z) + 1));
            float acc2 = tanh_approx(q0.x + w0.x) + tanh_approx(q0.y + w0.y) +
                         tanh_approx(q1.x + w0.z) + tanh_approx(q1.y + w0.w) +
                         tanh_approx(q2.x + w1.x) + tanh_approx(q2.y + w1.y) +
                         tanh_approx(q3.x + w1.z) + tanh_approx(q3.y + w1.w);
#pragma unroll
            for (int o = 16; o; o >>= 1) {
                acc1 += __shfl_xor_sync(0xffffffffu, acc1, o);
                acc2 += __shfl_xor_sync(0xffffffffu, acc2, o);
            }
            if (lane == 0) {
                sh_e[s1 - sbase] = acc1;
                sh_e[s2 - sbase] = acc2;
            }
        }
    }
    __syncthreads();

    // Local softmax over this chunk's 128 energies
    {
        float e = (tid < 128) ? sh_e[tid] : -1e30f;
        float m = e;
#pragma unroll
        for (int o = 16; o; o >>= 1) m = fmaxf(m, __shfl_xor_sync(0xffffffffu, m, o));
        if (lane == 0) sh_red[warp] = m;
        __syncthreads();
        float mx = sh_red[0];
#pragma unroll
        for (int i = 1; i < 16; i++) mx = fmaxf(mx, sh_red[i]);
        float w = __expf(e - mx);   // 0 for tid >= 128
        float ws = w;
#pragma unroll
        for (int o = 16; o; o >>= 1) ws += __shfl_xor_sync(0xffffffffu, ws, o);
        if (lane == 0) sh_sum[warp] = ws;
        __syncthreads();
        float total = 0.f;
#pragma unroll
        for (int i = 0; i < 16; i++) total += sh_sum[i];
        if (tid < 128) sh_e[tid] = w;           // unnormalized weights
        if (tid == 0) g_stats[c][b] = make_float2(mx, total);
    }
    __syncthreads();

    // Ctx partial (unnormalized) over this chunk's 128 s
    {
        int e8 = tid & 31;
        int sp = tid >> 5;
        const uint4* mb = (const uint4*)(g_memt + (size_t)b * SS * DD);
        float acc[8];
#pragma unroll
        for (int j = 0; j < 8; j++) acc[j] = 0.f;
#pragma unroll
        for (int k = 0; k < 8; k++) {
            int sl = sp + k * 16;               // local s 0..127
            int s = c * 128 + sl;
            uint4 v = ldg_el(&mb[s * 32 + e8], pol);
            float a = sh_e[sl];
            float2 f0 = __half22float2(*(__half2*)&v.x);
            float2 f1 = __half22float2(*(((__half2*)&v.x) + 1));
            float2 f2 = __half22float2(*(__half2*)&v.z);
            float2 f3 = __half22float2(*(((__half2*)&v.z) + 1));
            acc[0] = fmaf(a, f0.x, acc[0]);
            acc[1] = fmaf(a, f0.y, acc[1]);
            acc[2] = fmaf(a, f1.x, acc[2]);
            acc[3] = fmaf(a, f1.y, acc[3]);
            acc[4] = fmaf(a, f2.x, acc[4]);
            acc[5] = fmaf(a, f2.y, acc[5]);
            acc[6] = fmaf(a, f3.x, acc[6]);
            acc[7] = fmaf(a, f3.y, acc[7]);
        }
#pragma unroll
        for (int j = 0; j < 8; j++) sh_ctxp[sp][e8 * 8 + j] = acc[j];
    }
    __syncthreads();
    if (tid < DD) {
        float s = 0.f;
#pragma unroll
        for (int i = 0; i < 16; i++) s += sh_ctxp[i][tid];
        g_ctxp[c][b * DD + tid] = s;
    }
}

// ---------------- per-step gate GEMM via HMMA: sources ctx (kz=0, with softmax combine) and h (kz=1) ----------------
// grid (32 n-tiles, 4 m-tiles, 2 kz), 128 thr.
__global__ __launch_bounds__(128) void k_gemm(int hp) {
    __shared__ __align__(16) __half sA[32][264];
    __shared__ __align__(16) __half sB[32][264];
    __shared__ float sh_scale[32][4];

    int tid = threadIdx.x;
    int lane = tid & 31;
    int warp = tid >> 5;
    int n0 = blockIdx.x * 32;
    int m0 = blockIdx.y * 32;
    int kz = blockIdx.z;       // 0: ctx, 1: h

    // per-batch softmax-combine scales (exact): scale_c = e^{mx_c - M} / D
    if (kz == 0 && tid < 32) {
        int row = m0 + tid;
        float2 s0 = g_stats[0][row], s1 = g_stats[1][row], s2 = g_stats[2][row], s3 = g_stats[3][row];
        float M = fmaxf(fmaxf(s0.x, s1.x), fmaxf(s2.x, s3.x));
        float e0 = __expf(s0.x - M), e1 = __expf(s1.x - M);
        float e2 = __expf(s2.x - M), e3 = __expf(s3.x - M);
        float D = s0.y * e0 + s1.y * e1 + s2.y * e2 + s3.y * e3;
        float inv = __fdividef(1.f, D);
        sh_scale[tid][0] = e0 * inv;
        sh_scale[tid][1] = e1 * inv;
        sh_scale[tid][2] = e2 * inv;
        sh_scale[tid][3] = e3 * inv;
    }
    __syncthreads();

    // stage A
    {
        const float4* hsrc = (const float4*)g_h[hp];
        const float4* c0p = (const float4*)g_ctxp[0];
        const float4* c1p = (const float4*)g_ctxp[1];
        const float4* c2p = (const float4*)g_ctxp[2];
        const float4* c3p = (const float4*)g_ctxp[3];
#pragma unroll
        for (int i = 0; i < 16; i++) {
            int idx = tid + i * 128;      // 0..2047
            int row = idx >> 6;           // 64 float4 per row
            int c4 = idx & 63;
            int a4 = (m0 + row) * 64 + c4;
            float4 v;
            if (kz == 0) {
                float sc0 = sh_scale[row][0], sc1 = sh_scale[row][1];
                float sc2 = sh_scale[row][2], sc3 = sh_scale[row][3];
                float4 x0 = c0p[a4], x1 = c1p[a4], x2 = c2p[a4], x3 = c3p[a4];
                v.x = fmaf(x3.x, sc3, fmaf(x2.x, sc2, fmaf(x1.x, sc1, x0.x * sc0)));
                v.y = fmaf(x3.y, sc3, fmaf(x2.y, sc2, fmaf(x1.y, sc1, x0.y * sc0)));
                v.z = fmaf(x3.z, sc3, fmaf(x2.z, sc2, fmaf(x1.z, sc1, x0.z * sc0)));
                v.w = fmaf(x3.w, sc3, fmaf(x2.w, sc2, fmaf(x1.w, sc1, x0.w * sc0)));
            } else {
                v = hsrc[a4];
            }
            *(__half2*)&sA[row][c4 * 4]     = __floats2half2_rn(v.x, v.y);
            *(__half2*)&sA[row][c4 * 4 + 2] = __floats2half2_rn(v.z, v.w);
        }
    }
    // stage B: g_w16 cols 256 + kz*256 .. +255
    {
        const uint4* wb = (const uint4*)g_w16;
        int coff = 32 + kz * 32;
#pragma unroll
        for (int i = 0; i < 8; i++) {
            int idx = tid + i * 128;
            int row = idx >> 5;
            int c4 = idx & 31;
            uint4 v = wb[(size_t)(n0 + row) * 96 + coff + c4];
            *(uint4*)&sB[row][c4 * 8] = v;
        }
    }
    __syncthreads();

    int g = lane >> 2;
    int tg = lane & 3;
    int mw = (warp >> 1) * 16;
    int nw = (warp & 1) * 16;

    float d0[4] = {0.f, 0.f, 0.f, 0.f};
    float d1[4] = {0.f, 0.f, 0.f, 0.f};

#pragma unroll
    for (int ks = 0; ks < 16; ks++) {
        int kc = ks * 16 + tg * 2;
        uint32_t a0 = *(const uint32_t*)&sA[mw + g][kc];
        uint32_t a1 = *(const uint32_t*)&sA[mw + g + 8][kc];
        uint32_t a2 = *(const uint32_t*)&sA[mw + g][kc + 8];
        uint32_t a3 = *(const uint32_t*)&sA[mw + g + 8][kc + 8];
        uint32_t b0 = *(const uint32_t*)&sB[nw + g][kc];
        uint32_t b1 = *(const uint32_t*)&sB[nw + g][kc + 8];
        uint32_t b2 = *(const uint32_t*)&sB[nw + 8 + g][kc];
        uint32_t b3 = *(const uint32_t*)&sB[nw + 8 + g][kc + 8];

        asm volatile(
            "mma.sync.aligned.m16n8k16.row.col.f32.f16.f16.f32 "
            "{%0,%1,%2,%3}, {%4,%5,%6,%7}, {%8,%9}, {%0,%1,%2,%3};\n"
            : "+f"(d0[0]), "+f"(d0[1]), "+f"(d0[2]), "+f"(d0[3])
            : "r"(a0), "r"(a1), "r"(a2), "r"(a3), "r"(b0), "r"(b1));
        asm volatile(
            "mma.sync.aligned.m16n8k16.row.col.f32.f16.f16.f32 "
            "{%0,%1,%2,%3}, {%4,%5,%6,%7}, {%8,%9}, {%0,%1,%2,%3};\n"
            : "+f"(d1[0]), "+f"(d1[1]), "+f"(d1[2]), "+f"(d1[3])
            : "r"(a0), "r"(a1), "r"(a2), "r"(a3), "r"(b2), "r"(b3));
    }

    {
        int r0 = m0 + mw + g;
        int r1 = r0 + 8;
        int c0 = n0 + nw + tg * 2;
        float* gp = g_gp[kz];
        *(float2*)&gp[(size_t)r0 * GG + c0]     = make_float2(d0[0], d0[1]);
        *(float2*)&gp[(size_t)r1 * GG + c0]     = make_float2(d0[2], d0[3]);
        *(float2*)&gp[(size_t)r0 * GG + c0 + 8] = make_float2(d1[0], d1[1]);
        *(float2*)&gp[(size_t)r1 * GG + c0 + 8] = make_float2(d1[2], d1[3]);
    }
}

// ---------------- final LSTM cell: emits out[TT-1] ----------------
__global__ __launch_bounds__(256) void k_cell_final(const float* __restrict__ b_ih,
                                                    const float* __restrict__ b_hh,
                                                    float* __restrict__ out_t,
                                                    int rp) {
    int idx = blockIdx.x * blockDim.x + threadIdx.x;
    int b = idx >> 8;
    int hd = idx & 255;
    size_t base = (size_t)b * GG;
    size_t pre = ((size_t)(TT - 1) * BB + b) * GG;

    float vi = b_ih[hd] + b_hh[hd] + g_gpre[pre + hd];
    float vf = b_ih[hd + 256] + b_hh[hd + 256] + g_gpre[pre + hd + 256];
    float vg = b_ih[hd + 512] + b_hh[hd + 512] + g_gpre[pre + hd + 512];
    float vo = b_ih[hd + 768] + b_hh[hd + 768] + g_gpre[pre + hd + 768];
#pragma unroll
    for (int p = 0; p < NKZ; p++) {
        vi += g_gp[p][base + hd];
        vf += g_gp[p][base + hd + 256];
        vg += g_gp[p][base + hd + 512];
        vo += g_gp[p][base + hd + 768];
    }

    float gi = fast_sigmoid(vi);
    float gf = fast_sigmoid(vf);
    float gc = fast_tanh(vg);
    float go = fast_sigmoid(vo);
    float c = gf * g_c[rp][idx] + gi * gc;
    float h = go * fast_tanh(c);
    out_t[idx] = h;
}

// ---------------- launch ----------------
// Graph node count: 1 (k_pre) + 1 (k_pregemm) + 255*2 (k_att, k_gemm) + 1 (final) = 513
extern "C" void kernel_launch(void* const* d_in, const int* in_sizes, int n_in,
                              void* d_out, int out_size) {
    const float* tgt    = (const float*)d_in[0];  // (T,B,256)
    const float* memory = (const float*)d_in[1];  // (S,B,256)
    const float* W_attn = (const float*)d_in[2];  // (256,512)
    const float* b_attn = (const float*)d_in[3];  // (256,)
    const float* W_ih   = (const float*)d_in[4];  // (1024,512)
    const float* W_hh   = (const float*)d_in[5];  // (1024,256)
    const float* b_ih   = (const float*)d_in[6];  // (1024,)
    const float* b_hh   = (const float*)d_in[7];  // (1024,)
    float* out = (float*)d_out;                   // (T,B,256)

    (void)in_sizes; (void)n_in; (void)out_size;

    dim3 gmp(4, 1024);
    k_pre<<<gmp, 256>>>(memory, W_attn, b_attn, W_ih, W_hh, out);

    dim3 gpg(32, 1024);
    k_pregemm<<<gpg, 128>>>(tgt);

    for (int t = 1; t < TT; t++) {
        dim3 ge(4, BB);
        k_att<<<ge, 512>>>(W_attn, b_ih, b_hh, out + (size_t)(t - 1) * BB * DD, t);
        dim3 gg(32, 4, NKZ);
        k_gemm<<<gg, 128>>>((t - 1) & 1);
    }
    k_cell_final<<<128, 256>>>(b_ih, b_hh, out + (size_t)(TT - 1) * BB * DD, (TT) & 1);
}